// round 16
// baseline (speedup 1.0000x reference)
#include <cuda_runtime.h>
#include <cuda_bf16.h>
#include <cuda_fp16.h>
#include <cstdint>

#define BATCH 4
#define CTX   2048
#define NEMB  1024
#define NH    16
#define HS    64
#define DM    1024
#define FF    4096
#define MTOT  (BATCH*CTX)   // 8192

typedef __half f16;

// ================= scratch =================
__device__ f16 g_q16[(size_t)BATCH*NH*CTX*HS];
__device__ f16 g_k16[(size_t)BATCH*NH*CTX*HS];
__device__ f16 g_v16[(size_t)BATCH*NH*CTX*HS];
__device__ f16 g_x16h[(size_t)MTOT*NEMB];
__device__ f16 g_a16h[(size_t)MTOT*DM];
__device__ f16 g_h16h[(size_t)MTOT*FF];
// weights fp16, K-major [K, N] (same layout as source, GEMM uses ldmatrix.trans)
__device__ f16 g_bq16[(size_t)NEMB*3*DM];   // [C, 3*DM]
__device__ f16 g_w116[(size_t)DM*FF];       // [DM, FF]
__device__ f16 g_w216[(size_t)FF*DM];       // [FF, DM]

#define ASCALE 256.f
#define INVASC (1.f/256.f)
#define SCLQK  0.180336884f   // 0.125 * log2(e)

__device__ __forceinline__ uint32_t pack2h(float a, float b) {
    __half2 p = __floats2half2_rn(a, b);
    return *reinterpret_cast<uint32_t*>(&p);
}
__device__ __forceinline__ uint32_t smem_u32(const void* p) {
    uint32_t a;
    asm("{ .reg .u64 t; cvta.to.shared.u64 t, %1; cvt.u32.u64 %0, t; }" : "=r"(a) : "l"(p));
    return a;
}
__device__ __forceinline__ void cp16(uint32_t dst, const void* src) {
    asm volatile("cp.async.cg.shared.global [%0], [%1], 16;" :: "r"(dst), "l"(src));
}
#define CP_COMMIT() asm volatile("cp.async.commit_group;" ::: "memory")
#define CP_WAIT(n)  asm volatile("cp.async.wait_group %0;" :: "n"(n) : "memory")

__device__ __forceinline__ void ldm4(uint32_t* r, uint32_t addr) {
    asm volatile("ldmatrix.sync.aligned.m8n8.x4.shared.b16 {%0,%1,%2,%3}, [%4];"
        : "=r"(r[0]), "=r"(r[1]), "=r"(r[2]), "=r"(r[3]) : "r"(addr));
}
__device__ __forceinline__ void ldm4t(uint32_t* r, uint32_t addr) {
    asm volatile("ldmatrix.sync.aligned.m8n8.x4.trans.shared.b16 {%0,%1,%2,%3}, [%4];"
        : "=r"(r[0]), "=r"(r[1]), "=r"(r[2]), "=r"(r[3]) : "r"(addr));
}
__device__ __forceinline__ void mma_f16(float* d, const uint32_t* a, const uint32_t* b) {
    asm volatile("mma.sync.aligned.m16n8k16.row.col.f32.f16.f16.f32 "
        "{%0,%1,%2,%3}, {%4,%5,%6,%7}, {%8,%9}, {%0,%1,%2,%3};"
        : "+f"(d[0]), "+f"(d[1]), "+f"(d[2]), "+f"(d[3])
        : "r"(a[0]), "r"(a[1]), "r"(a[2]), "r"(a[3]), "r"(b[0]), "r"(b[1]));
}

// ================= convert kernels (pure streaming, no transpose) =================
// x -> fp16, scaled x256
__global__ __launch_bounds__(256) void conv_x_kernel(const float* __restrict__ x,
                                                     f16* __restrict__ hi)
{
    size_t i = (size_t)blockIdx.x * 256 + threadIdx.x;
    float4 v = ((const float4*)x)[i];
    ((uint2*)hi)[i] = make_uint2(pack2h(v.x * ASCALE, v.y * ASCALE),
                                 pack2h(v.z * ASCALE, v.w * ASCALE));
}

// W1 [DM,FF] and W2 [FF,DM] -> fp16 same layout. blockIdx.y selects.
__global__ __launch_bounds__(256) void conv_w_kernel(const float* __restrict__ W1,
                                                     f16* __restrict__ o1,
                                                     const float* __restrict__ W2,
                                                     f16* __restrict__ o2)
{
    const float* src = blockIdx.y ? W2 : W1;
    f16* dst = blockIdx.y ? o2 : o1;
    size_t i = (size_t)blockIdx.x * 256 + threadIdx.x;
    float4 v = ((const float4*)src)[i];
    ((uint2*)dst)[i] = make_uint2(pack2h(v.x, v.y), pack2h(v.z, v.w));
}

// Wq/Wk/Wv [H,C,D] -> bq16 [c][sel*1024 + h*64 + d] fp16
__global__ __launch_bounds__(256) void conv_qkv_kernel(const float* __restrict__ Wq,
                                                       const float* __restrict__ Wk,
                                                       const float* __restrict__ Wv,
                                                       f16* __restrict__ out)
{
    int sel = blockIdx.y;
    const float* W = (sel == 0 ? Wq : sel == 1 ? Wk : Wv);
    size_t i = (size_t)blockIdx.x * 256 + threadIdx.x;   // float4 id
    float4 v = ((const float4*)W)[i];
    size_t i4 = i * 4;                 // (h*NEMB + c)*HS + d
    int h = (int)(i4 >> 16);           // / (NEMB*HS)
    int c = (int)((i4 >> 6) & 1023);
    int d = (int)(i4 & 63);
    size_t o = (size_t)c * (3 * DM) + sel * DM + h * HS + d;
    *(uint2*)(out + o) = make_uint2(pack2h(v.x, v.y), pack2h(v.z, v.w));
}

// ================= single-fp16 GEMM, 128x256 CTA, BK=128, 2-stage, trans-B =================
// D = Ah * B, A [M,K] row-major pre-scaled x256, B [K,N] K-major (ldmatrix.trans).
// MODE 0: scatter -> q/k/v single fp16, [B,H,T,D]
// MODE 1: +bias, write fp16 x256 (FFN1 -> h)
// MODE 2: +bias, relu, write fp32 (FFN2 -> out)
#define ROWA    272           // A row: 128 fp16 = 256B + 16B pad
#define ROWBB   528           // B row: 256 fp16 = 512B + 16B pad
#define TA      (128*ROWA)    // 34816
#define TB      (128*ROWBB)   // 67584
#define OFF_BH  (TA)
#define STAGE_B (TA + TB)     // 102400
#define NSTAGE  2
#define GEMM_SMEM (NSTAGE*STAGE_B)   // 204800

template <int MODE>
__global__ __launch_bounds__(256, 1)
void gemm_f16(const f16* __restrict__ Ahi,
              const f16* __restrict__ Bk,
              const float* __restrict__ bias,
              float* __restrict__ out_f, f16* __restrict__ out_hi,
              f16* __restrict__ qq, f16* __restrict__ kk, f16* __restrict__ vv,
              int N, int K)
{
    extern __shared__ char smem[];
    uint32_t sb = smem_u32(smem);

    int tid = threadIdx.x, wid = tid >> 5, lid = tid & 31;
    int wm = wid >> 2, wn = wid & 3;          // warp tile 64(M) x 64(N)
    int bx = blockIdx.x, by = blockIdx.y;

    const f16* aH = Ahi + (size_t)by * 128 * K;
    const f16* bB = Bk + (size_t)bx * 256;    // column offset in [K,N]

    float acc[4][8][4];
#pragma unroll
    for (int i = 0; i < 4; i++)
#pragma unroll
        for (int j = 0; j < 8; j++)
#pragma unroll
            for (int l = 0; l < 4; l++) acc[i][j][l] = 0.f;

    int ITERS = K >> 7;

#define ISSUE(st, k0) do {                                                         \
        uint32_t _b = sb + (st) * STAGE_B;                                         \
        _Pragma("unroll")                                                          \
        for (int _i = 0; _i < 8; _i++) {                                           \
            int _c = tid + _i * 256; int _r = _c >> 4, _q = _c & 15;               \
            cp16(_b + (uint32_t)(_r * ROWA + _q * 16),                             \
                 aH + (size_t)_r * K + (k0) + _q * 8);                             \
        }                                                                          \
        _Pragma("unroll")                                                          \
        for (int _i = 0; _i < 16; _i++) {                                          \
            int _c = tid + _i * 256; int _r = _c >> 5, _q = _c & 31;               \
            cp16(_b + OFF_BH + (uint32_t)(_r * ROWBB + _q * 16),                   \
                 bB + (size_t)((k0) + _r) * N + _q * 8);                           \
        }                                                                          \
    } while (0)

    ISSUE(0, 0); CP_COMMIT();

    int g = lid >> 3, rr = lid & 7;
    uint32_t a_row_off = (uint32_t)(((g & 1) * 8 + rr) * ROWA + (g >> 1) * 16);
    uint32_t b_trn_off = (uint32_t)(((g & 1) * 8 + rr) * ROWBB + (g >> 1) * 16);

    for (int it = 0; it < ITERS; it++) {
        CP_WAIT(0);                 // stage it resident
        __syncthreads();            // all warps done with the other stage
        if (it + 1 < ITERS) { ISSUE((it + 1) & 1, (it + 1) * 128); CP_COMMIT(); }

        uint32_t base = sb + (it & 1) * STAGE_B;
#pragma unroll
        for (int ks = 0; ks < 8; ks++) {
            uint32_t ah[4][4], bh[4][4];
#pragma unroll
            for (int mi = 0; mi < 4; mi++)
                ldm4(ah[mi], base + (uint32_t)((wm * 64 + mi * 16) * ROWA + ks * 32) + a_row_off);
#pragma unroll
            for (int p = 0; p < 4; p++)
                ldm4t(bh[p], base + OFF_BH + (uint32_t)((ks * 16) * ROWBB + (wn * 64 + p * 16) * 2) + b_trn_off);
#pragma unroll
            for (int mi = 0; mi < 4; mi++)
#pragma unroll
                for (int ni = 0; ni < 8; ni++)
                    mma_f16(acc[mi][ni], ah[mi], &bh[ni >> 1][(ni & 1) * 2]);
        }
    }
#undef ISSUE

    // ---------------- epilogue (rescale 1/256) ----------------
    int t4 = lid >> 2, t2 = (lid & 3) * 2;
#pragma unroll
    for (int mi = 0; mi < 4; mi++) {
#pragma unroll
        for (int ni = 0; ni < 8; ni++) {
            int n = bx * 256 + wn * 64 + ni * 8 + t2;
            int m0 = by * 128 + wm * 64 + mi * 16 + t4;
            float bn0 = 0.f, bn1 = 0.f;
            if (MODE != 0) { bn0 = bias[n]; bn1 = bias[n + 1]; }
#pragma unroll
            for (int half = 0; half < 2; half++) {
                int m = m0 + half * 8;
                float v0 = acc[mi][ni][half * 2]     * INVASC;
                float v1 = acc[mi][ni][half * 2 + 1] * INVASC;
                if (MODE == 0) {
                    int b = m >> 11, t = m & (CTX - 1);
                    int sel = n >> 10, hh = (n & 1023) >> 6, d0 = n & 63;
                    f16* dst = (sel == 0) ? qq : (sel == 1 ? kk : vv);
                    size_t o = ((size_t)(b * NH + hh) * CTX + t) * HS + d0;
                    *(uint32_t*)(dst + o) = pack2h(v0, v1);
                } else if (MODE == 1) {
                    float s0 = (v0 + bn0) * ASCALE;
                    float s1 = (v1 + bn1) * ASCALE;
                    size_t o = (size_t)m * N + n;
                    *(uint32_t*)(out_hi + o) = pack2h(s0, s1);
                } else {
                    v0 = fmaxf(v0 + bn0, 0.f);
                    v1 = fmaxf(v1 + bn1, 0.f);
                    *(float2*)(out_f + (size_t)m * N + n) = make_float2(v0, v1);
                }
            }
        }
    }
}

// ================= mma.sync causal flash attention (single fp16, exp2 softmax) =================
#define PADB   144
#define QTILE  (128*PADB)       // 18432
#define KVTILE (64*PADB)        // 9216
#define ASTAGE (2*KVTILE)       // 18432
#define ATTN_SMEM (QTILE + 2*ASTAGE)   // 55296

__global__ __launch_bounds__(256, 2)
void attn_mma()
{
    extern __shared__ char smem[];
    uint32_t sb = smem_u32(smem);
    int tid = threadIdx.x, wid = tid >> 5, lid = tid & 31;
    int qt = blockIdx.x, h = blockIdx.y, b = blockIdx.z;
    int q0 = qt * 128;
    int wm = wid;
    int g = lid >> 3, rr = lid & 7;
    uint32_t a_off = (uint32_t)(((g & 1) * 8 + rr) * PADB + (g >> 1) * 16);
    uint32_t b_off = (uint32_t)(((g >> 1) * 8 + rr) * PADB + (g & 1) * 16);
    int t4 = lid >> 2, t2 = lid & 3;

    size_t hb = (size_t)(b * NH + h);
    const f16* qB = g_q16 + hb * CTX * HS;
    const f16* kB = g_k16 + hb * CTX * HS;
    const f16* vB = g_v16 + hb * CTX * HS;

    // Q tile (128 x 64)
#pragma unroll
    for (int i = 0; i < 4; i++) {
        int idx = tid + i * 256;
        int r = idx >> 3, ch = idx & 7;
        cp16(sb + (uint32_t)(r * PADB + ch * 16), qB + (size_t)(q0 + r) * HS + ch * 8);
    }
    CP_COMMIT();

#define LOAD_TILE(st, kb_) do {                                            \
        uint32_t bs = sb + QTILE + (st) * ASTAGE;                          \
        for (int i_ = 0; i_ < 2; i_++) {                                   \
            int idx_ = tid + i_ * 256;                                     \
            int r_ = idx_ >> 3, ch_ = idx_ & 7;                            \
            uint32_t so_ = (uint32_t)(r_ * PADB + ch_ * 16);               \
            size_t kg_ = (size_t)((kb_) + r_) * HS + ch_ * 8;              \
            cp16(bs + so_, kB + kg_);                                      \
            cp16(bs + KVTILE + so_, vB + kg_);                             \
        } } while (0)

    LOAD_TILE(0, 0);
    CP_COMMIT();

    uint32_t qf[4][4];
    float of[8][4];
#pragma unroll
    for (int i = 0; i < 8; i++)
#pragma unroll
        for (int j = 0; j < 4; j++) of[i][j] = 0.f;
    float m0 = -1e30f, m1 = -1e30f, l0 = 0.f, l1 = 0.f;
    bool qload = false;

    int nkt = 2 * qt + 2;
    for (int kt = 0; kt < nkt; kt++) {
        int kb = kt * 64;
        CP_WAIT(0);
        __syncthreads();
        if (kt + 1 < nkt) { LOAD_TILE((kt + 1) & 1, kb + 64); CP_COMMIT(); }
        if (!qload) {
#pragma unroll
            for (int ks = 0; ks < 4; ks++)
                ldm4(qf[ks], sb + (uint32_t)((wm * 16) * PADB + ks * 32) + a_off);
            qload = true;
        }
        if (q0 + wm * 16 + 15 >= kb) {
            uint32_t base = sb + QTILE + (kt & 1) * ASTAGE;
            float sf[8][4];
#pragma unroll
            for (int i = 0; i < 8; i++)
#pragma unroll
                for (int j = 0; j < 4; j++) sf[i][j] = 0.f;

#pragma unroll
            for (int ks = 0; ks < 4; ks++) {
                uint32_t bh[4][4];
#pragma unroll
                for (int p = 0; p < 4; p++)
                    ldm4(bh[p], base + (uint32_t)((p * 16) * PADB + ks * 32) + b_off);
#pragma unroll
                for (int ni = 0; ni < 8; ni++)
                    mma_f16(sf[ni], qf[ks], &bh[ni >> 1][(ni & 1) * 2]);
            }

            int row0 = q0 + wm * 16 + t4, row1 = row0 + 8;
            bool needm = (kb + 63 > q0 + wm * 16);
            float mx0 = -1e30f, mx1 = -1e30f;
#pragma unroll
            for (int ni = 0; ni < 8; ni++) {
                int c = kb + ni * 8 + t2 * 2;
                float s0 = sf[ni][0] * SCLQK, s1 = sf[ni][1] * SCLQK;
                float s2 = sf[ni][2] * SCLQK, s3 = sf[ni][3] * SCLQK;
                if (needm) {
                    if (c > row0)     s0 = -1e30f;
                    if (c + 1 > row0) s1 = -1e30f;
                    if (c > row1)     s2 = -1e30f;
                    if (c + 1 > row1) s3 = -1e30f;
                }
                sf[ni][0] = s0; sf[ni][1] = s1; sf[ni][2] = s2; sf[ni][3] = s3;
                mx0 = fmaxf(mx0, fmaxf(s0, s1));
                mx1 = fmaxf(mx1, fmaxf(s2, s3));
            }
            mx0 = fmaxf(mx0, __shfl_xor_sync(0xffffffffu, mx0, 1));
            mx0 = fmaxf(mx0, __shfl_xor_sync(0xffffffffu, mx0, 2));
            mx1 = fmaxf(mx1, __shfl_xor_sync(0xffffffffu, mx1, 1));
            mx1 = fmaxf(mx1, __shfl_xor_sync(0xffffffffu, mx1, 2));
            float nm0 = fmaxf(m0, mx0), nm1 = fmaxf(m1, mx1);
            float cr0 = exp2f(m0 - nm0), cr1 = exp2f(m1 - nm1);
            m0 = nm0; m1 = nm1;
            l0 *= cr0; l1 *= cr1;
#pragma unroll
            for (int ni = 0; ni < 8; ni++) {
                float p0 = exp2f(sf[ni][0] - m0), p1 = exp2f(sf[ni][1] - m0);
                float p2 = exp2f(sf[ni][2] - m1), p3 = exp2f(sf[ni][3] - m1);
                sf[ni][0] = p0; sf[ni][1] = p1; sf[ni][2] = p2; sf[ni][3] = p3;
                l0 += p0 + p1; l1 += p2 + p3;
                of[ni][0] *= cr0; of[ni][1] *= cr0; of[ni][2] *= cr1; of[ni][3] *= cr1;
            }

#pragma unroll
            for (int ks2 = 0; ks2 < 4; ks2++) {
                int n0b = 2 * ks2, n1b = n0b + 1;
                uint32_t pah[4];
                pah[0] = pack2h(sf[n0b][0], sf[n0b][1]);
                pah[1] = pack2h(sf[n0b][2], sf[n0b][3]);
                pah[2] = pack2h(sf[n1b][0], sf[n1b][1]);
                pah[3] = pack2h(sf[n1b][2], sf[n1b][3]);
                uint32_t vh[4][4];
#pragma unroll
                for (int p = 0; p < 4; p++)
                    ldm4t(vh[p], base + KVTILE + (uint32_t)((ks2 * 16) * PADB + p * 32) + a_off);
#pragma unroll
                for (int ni = 0; ni < 8; ni++)
                    mma_f16(of[ni], pah, &vh[ni >> 1][(ni & 1) * 2]);
            }
        }
    }
#undef LOAD_TILE

    l0 += __shfl_xor_sync(0xffffffffu, l0, 1);
    l0 += __shfl_xor_sync(0xffffffffu, l0, 2);
    l1 += __shfl_xor_sync(0xffffffffu, l1, 1);
    l1 += __shfl_xor_sync(0xffffffffu, l1, 2);
    float inv0 = ASCALE / l0, inv1 = ASCALE / l1;

    int row0 = q0 + wm * 16 + t4;
#pragma unroll
    for (int ni = 0; ni < 8; ni++) {
        int col = h * HS + ni * 8 + t2 * 2;
        float s0 = of[ni][0] * inv0, s1 = of[ni][1] * inv0;
        float s2 = of[ni][2] * inv1, s3 = of[ni][3] * inv1;
        size_t o0 = ((size_t)(b * CTX) + row0) * DM + col;
        size_t o1 = o0 + (size_t)8 * DM;
        *(uint32_t*)(g_a16h + o0) = pack2h(s0, s1);
        *(uint32_t*)(g_a16h + o1) = pack2h(s2, s3);
    }
}

// ================= launch =================
extern "C" void kernel_launch(void* const* d_in, const int* in_sizes, int n_in,
                              void* d_out, int out_size)
{
    const float* x  = (const float*)d_in[0];
    const float* Wq = (const float*)d_in[1];
    const float* Wk = (const float*)d_in[2];
    const float* Wv = (const float*)d_in[3];
    const float* W1 = (const float*)d_in[4];
    const float* b1 = (const float*)d_in[5];
    const float* W2 = (const float*)d_in[6];
    const float* b2 = (const float*)d_in[7];
    float* out = (float*)d_out;

    f16 *q16, *k16, *v16;
    f16 *x16h, *a16h, *h16h, *bq16, *w116, *w216;
    cudaGetSymbolAddress((void**)&q16, g_q16);
    cudaGetSymbolAddress((void**)&k16, g_k16);
    cudaGetSymbolAddress((void**)&v16, g_v16);
    cudaGetSymbolAddress((void**)&x16h, g_x16h);
    cudaGetSymbolAddress((void**)&a16h, g_a16h);
    cudaGetSymbolAddress((void**)&h16h, g_h16h);
    cudaGetSymbolAddress((void**)&bq16, g_bq16);
    cudaGetSymbolAddress((void**)&w116, g_w116);
    cudaGetSymbolAddress((void**)&w216, g_w216);

    cudaFuncSetAttribute((const void*)gemm_f16<0>, cudaFuncAttributeMaxDynamicSharedMemorySize, GEMM_SMEM);
    cudaFuncSetAttribute((const void*)gemm_f16<1>, cudaFuncAttributeMaxDynamicSharedMemorySize, GEMM_SMEM);
    cudaFuncSetAttribute((const void*)gemm_f16<2>, cudaFuncAttributeMaxDynamicSharedMemorySize, GEMM_SMEM);
    cudaFuncSetAttribute(attn_mma, cudaFuncAttributeMaxDynamicSharedMemorySize, ATTN_SMEM);

    // conversions (pure streaming)
    conv_x_kernel<<<(size_t)MTOT * NEMB / 1024, 256>>>(x, x16h);
    conv_qkv_kernel<<<dim3(NEMB * DM / 1024, 3), 256>>>(Wq, Wk, Wv, bq16);
    conv_w_kernel<<<dim3((size_t)DM * FF / 1024, 2), 256>>>(W1, w116, W2, w216);

    // QKV: [8192,1024] @ [1024,3072] -> q/k/v single fp16 [B,H,T,D]
    gemm_f16<0><<<dim3(3 * DM / 256, MTOT / 128), 256, GEMM_SMEM>>>(
        x16h, bq16, nullptr,
        nullptr, nullptr,
        q16, k16, v16, 3 * DM, NEMB);

    // attention -> att fp16 x256
    attn_mma<<<dim3(CTX / 128, NH, BATCH), 256, ATTN_SMEM>>>();

    // FFN1: [8192,1024] @ [1024,4096] + b1 -> h fp16 x256
    gemm_f16<1><<<dim3(FF / 256, MTOT / 128), 256, GEMM_SMEM>>>(
        a16h, w116, b1,
        nullptr, h16h,
        nullptr, nullptr, nullptr, FF, DM);

    // FFN2: [8192,4096] @ [4096,1024] + b2, relu -> out
    gemm_f16<2><<<dim3(DM / 256, MTOT / 128), 256, GEMM_SMEM>>>(
        h16h, w216, b2,
        out, nullptr,
        nullptr, nullptr, nullptr, DM, FF);
}

// round 17
// speedup vs baseline: 1.0315x; 1.0315x over previous
#include <cuda_runtime.h>
#include <cuda_bf16.h>
#include <cuda_fp16.h>
#include <cstdint>

#define BATCH 4
#define CTX   2048
#define NEMB  1024
#define NH    16
#define HS    64
#define DM    1024
#define FF    4096
#define MTOT  (BATCH*CTX)   // 8192

typedef __half f16;

// ================= scratch =================
__device__ f16 g_q16[(size_t)BATCH*NH*CTX*HS];
__device__ f16 g_k16[(size_t)BATCH*NH*CTX*HS];
__device__ f16 g_v16[(size_t)BATCH*NH*CTX*HS];
__device__ f16 g_x16h[(size_t)MTOT*NEMB];
__device__ f16 g_a16h[(size_t)MTOT*DM];
__device__ f16 g_h16h[(size_t)MTOT*FF];
// weights fp16, K-major [K, N] (GEMM consumes via ldmatrix.trans)
__device__ f16 g_bq16[(size_t)NEMB*3*DM];   // [C, 3*DM]
__device__ f16 g_w116[(size_t)DM*FF];       // [DM, FF]
__device__ f16 g_w216[(size_t)FF*DM];       // [FF, DM]

#define ASCALE 256.f
#define INVASC (1.f/256.f)
#define SCLQK  0.180336884f   // 0.125 * log2(e)

__device__ __forceinline__ uint32_t pack2h(float a, float b) {
    __half2 p = __floats2half2_rn(a, b);
    return *reinterpret_cast<uint32_t*>(&p);
}
__device__ __forceinline__ uint32_t smem_u32(const void* p) {
    uint32_t a;
    asm("{ .reg .u64 t; cvta.to.shared.u64 t, %1; cvt.u32.u64 %0, t; }" : "=r"(a) : "l"(p));
    return a;
}
__device__ __forceinline__ void cp16(uint32_t dst, const void* src) {
    asm volatile("cp.async.cg.shared.global [%0], [%1], 16;" :: "r"(dst), "l"(src));
}
#define CP_COMMIT() asm volatile("cp.async.commit_group;" ::: "memory")
#define CP_WAIT(n)  asm volatile("cp.async.wait_group %0;" :: "n"(n) : "memory")

__device__ __forceinline__ void ldm4(uint32_t* r, uint32_t addr) {
    asm volatile("ldmatrix.sync.aligned.m8n8.x4.shared.b16 {%0,%1,%2,%3}, [%4];"
        : "=r"(r[0]), "=r"(r[1]), "=r"(r[2]), "=r"(r[3]) : "r"(addr));
}
__device__ __forceinline__ void ldm4t(uint32_t* r, uint32_t addr) {
    asm volatile("ldmatrix.sync.aligned.m8n8.x4.trans.shared.b16 {%0,%1,%2,%3}, [%4];"
        : "=r"(r[0]), "=r"(r[1]), "=r"(r[2]), "=r"(r[3]) : "r"(addr));
}
__device__ __forceinline__ void mma_f16(float* d, const uint32_t* a, const uint32_t* b) {
    asm volatile("mma.sync.aligned.m16n8k16.row.col.f32.f16.f16.f32 "
        "{%0,%1,%2,%3}, {%4,%5,%6,%7}, {%8,%9}, {%0,%1,%2,%3};"
        : "+f"(d[0]), "+f"(d[1]), "+f"(d[2]), "+f"(d[3])
        : "r"(a[0]), "r"(a[1]), "r"(a[2]), "r"(a[3]), "r"(b[0]), "r"(b[1]));
}

// ================= convert kernels (pure streaming, no transpose) =================
__global__ __launch_bounds__(256) void conv_x_kernel(const float* __restrict__ x,
                                                     f16* __restrict__ hi)
{
    size_t i = (size_t)blockIdx.x * 256 + threadIdx.x;
    float4 v = ((const float4*)x)[i];
    ((uint2*)hi)[i] = make_uint2(pack2h(v.x * ASCALE, v.y * ASCALE),
                                 pack2h(v.z * ASCALE, v.w * ASCALE));
}

__global__ __launch_bounds__(256) void conv_w_kernel(const float* __restrict__ W1,
                                                     f16* __restrict__ o1,
                                                     const float* __restrict__ W2,
                                                     f16* __restrict__ o2)
{
    const float* src = blockIdx.y ? W2 : W1;
    f16* dst = blockIdx.y ? o2 : o1;
    size_t i = (size_t)blockIdx.x * 256 + threadIdx.x;
    float4 v = ((const float4*)src)[i];
    ((uint2*)dst)[i] = make_uint2(pack2h(v.x, v.y), pack2h(v.z, v.w));
}

// Wq/Wk/Wv [H,C,D] -> bq16 [c][sel*1024 + h*64 + d] fp16
__global__ __launch_bounds__(256) void conv_qkv_kernel(const float* __restrict__ Wq,
                                                       const float* __restrict__ Wk,
                                                       const float* __restrict__ Wv,
                                                       f16* __restrict__ out)
{
    int sel = blockIdx.y;
    const float* W = (sel == 0 ? Wq : sel == 1 ? Wk : Wv);
    size_t i = (size_t)blockIdx.x * 256 + threadIdx.x;   // float4 id
    float4 v = ((const float4*)W)[i];
    size_t i4 = i * 4;                 // (h*NEMB + c)*HS + d
    int h = (int)(i4 >> 16);
    int c = (int)((i4 >> 6) & 1023);
    int d = (int)(i4 & 63);
    size_t o = (size_t)c * (3 * DM) + sel * DM + h * HS + d;
    *(uint2*)(out + o) = make_uint2(pack2h(v.x, v.y), pack2h(v.z, v.w));
}

// ===== single-fp16 GEMM, 128x256 CTA, 512 threads (16 warps, 32x64 warp tile), BK=128, 2-stage =====
// D = Ah * B, A [M,K] row-major pre-scaled x256, B [K,N] K-major (ldmatrix.trans).
// MODE 0: scatter -> q/k/v single fp16, [B,H,T,D]
// MODE 1: +bias, write fp16 x256 (FFN1 -> h)
// MODE 2: +bias, relu, write fp32 (FFN2 -> out)
#define ROWA    272           // A row: 128 fp16 = 256B + 16B pad
#define ROWBB   528           // B row: 256 fp16 = 512B + 16B pad
#define TA      (128*ROWA)    // 34816
#define TB      (128*ROWBB)   // 67584
#define OFF_BH  (TA)
#define STAGE_B (TA + TB)     // 102400
#define NSTAGE  2
#define GEMM_SMEM (NSTAGE*STAGE_B)   // 204800

template <int MODE>
__global__ __launch_bounds__(512, 1)
void gemm_f16(const f16* __restrict__ Ahi,
              const f16* __restrict__ Bk,
              const float* __restrict__ bias,
              float* __restrict__ out_f, f16* __restrict__ out_hi,
              f16* __restrict__ qq, f16* __restrict__ kk, f16* __restrict__ vv,
              int N, int K)
{
    extern __shared__ char smem[];
    uint32_t sb = smem_u32(smem);

    int tid = threadIdx.x, wid = tid >> 5, lid = tid & 31;
    int wm = wid >> 2, wn = wid & 3;          // warp grid 4(M) x 4(N); warp tile 32(M) x 64(N)
    int bx = blockIdx.x, by = blockIdx.y;

    const f16* aH = Ahi + (size_t)by * 128 * K;
    const f16* bB = Bk + (size_t)bx * 256;    // column offset in [K,N]

    float acc[2][8][4];
#pragma unroll
    for (int i = 0; i < 2; i++)
#pragma unroll
        for (int j = 0; j < 8; j++)
#pragma unroll
            for (int l = 0; l < 4; l++) acc[i][j][l] = 0.f;

    int ITERS = K >> 7;

#define ISSUE(st, k0) do {                                                         \
        uint32_t _b = sb + (st) * STAGE_B;                                         \
        _Pragma("unroll")                                                          \
        for (int _i = 0; _i < 4; _i++) {                                           \
            int _c = tid + _i * 512; int _r = _c >> 4, _q = _c & 15;               \
            cp16(_b + (uint32_t)(_r * ROWA + _q * 16),                             \
                 aH + (size_t)_r * K + (k0) + _q * 8);                             \
        }                                                                          \
        _Pragma("unroll")                                                          \
        for (int _i = 0; _i < 8; _i++) {                                           \
            int _c = tid + _i * 512; int _r = _c >> 5, _q = _c & 31;               \
            cp16(_b + OFF_BH + (uint32_t)(_r * ROWBB + _q * 16),                   \
                 bB + (size_t)((k0) + _r) * N + _q * 8);                           \
        }                                                                          \
    } while (0)

    ISSUE(0, 0); CP_COMMIT();

    int g = lid >> 3, rr = lid & 7;
    uint32_t a_row_off = (uint32_t)(((g & 1) * 8 + rr) * ROWA + (g >> 1) * 16);
    uint32_t b_trn_off = (uint32_t)(((g & 1) * 8 + rr) * ROWBB + (g >> 1) * 16);

    for (int it = 0; it < ITERS; it++) {
        CP_WAIT(0);                 // stage it resident
        __syncthreads();            // all warps done with the other stage
        if (it + 1 < ITERS) { ISSUE((it + 1) & 1, (it + 1) * 128); CP_COMMIT(); }

        uint32_t base = sb + (it & 1) * STAGE_B;
#pragma unroll
        for (int ks = 0; ks < 8; ks++) {
            uint32_t ah[2][4], bh[4][4];
#pragma unroll
            for (int mi = 0; mi < 2; mi++)
                ldm4(ah[mi], base + (uint32_t)((wm * 32 + mi * 16) * ROWA + ks * 32) + a_row_off);
#pragma unroll
            for (int p = 0; p < 4; p++)
                ldm4t(bh[p], base + OFF_BH + (uint32_t)((ks * 16) * ROWBB + (wn * 64 + p * 16) * 2) + b_trn_off);
#pragma unroll
            for (int mi = 0; mi < 2; mi++)
#pragma unroll
                for (int ni = 0; ni < 8; ni++)
                    mma_f16(acc[mi][ni], ah[mi], &bh[ni >> 1][(ni & 1) * 2]);
        }
    }
#undef ISSUE

    // ---------------- epilogue (rescale 1/256) ----------------
    int t4 = lid >> 2, t2 = (lid & 3) * 2;
#pragma unroll
    for (int mi = 0; mi < 2; mi++) {
#pragma unroll
        for (int ni = 0; ni < 8; ni++) {
            int n = bx * 256 + wn * 64 + ni * 8 + t2;
            int m0 = by * 128 + wm * 32 + mi * 16 + t4;
            float bn0 = 0.f, bn1 = 0.f;
            if (MODE != 0) { bn0 = bias[n]; bn1 = bias[n + 1]; }
#pragma unroll
            for (int half = 0; half < 2; half++) {
                int m = m0 + half * 8;
                float v0 = acc[mi][ni][half * 2]     * INVASC;
                float v1 = acc[mi][ni][half * 2 + 1] * INVASC;
                if (MODE == 0) {
                    int b = m >> 11, t = m & (CTX - 1);
                    int sel = n >> 10, hh = (n & 1023) >> 6, d0 = n & 63;
                    f16* dst = (sel == 0) ? qq : (sel == 1 ? kk : vv);
                    size_t o = ((size_t)(b * NH + hh) * CTX + t) * HS + d0;
                    *(uint32_t*)(dst + o) = pack2h(v0, v1);
                } else if (MODE == 1) {
                    float s0 = (v0 + bn0) * ASCALE;
                    float s1 = (v1 + bn1) * ASCALE;
                    size_t o = (size_t)m * N + n;
                    *(uint32_t*)(out_hi + o) = pack2h(s0, s1);
                } else {
                    v0 = fmaxf(v0 + bn0, 0.f);
                    v1 = fmaxf(v1 + bn1, 0.f);
                    *(float2*)(out_f + (size_t)m * N + n) = make_float2(v0, v1);
                }
            }
        }
    }
}

// ================= mma.sync causal flash attention (single fp16, exp2 softmax) =================
#define PADB   144
#define QTILE  (128*PADB)       // 18432
#define KVTILE (64*PADB)        // 9216
#define ASTAGE (2*KVTILE)       // 18432
#define ATTN_SMEM (QTILE + 2*ASTAGE)   // 55296

__global__ __launch_bounds__(256, 2)
void attn_mma()
{
    extern __shared__ char smem[];
    uint32_t sb = smem_u32(smem);
    int tid = threadIdx.x, wid = tid >> 5, lid = tid & 31;
    int qt = blockIdx.x, h = blockIdx.y, b = blockIdx.z;
    int q0 = qt * 128;
    int wm = wid;
    int g = lid >> 3, rr = lid & 7;
    uint32_t a_off = (uint32_t)(((g & 1) * 8 + rr) * PADB + (g >> 1) * 16);
    uint32_t b_off = (uint32_t)(((g >> 1) * 8 + rr) * PADB + (g & 1) * 16);
    int t4 = lid >> 2, t2 = lid & 3;

    size_t hb = (size_t)(b * NH + h);
    const f16* qB = g_q16 + hb * CTX * HS;
    const f16* kB = g_k16 + hb * CTX * HS;
    const f16* vB = g_v16 + hb * CTX * HS;

    // Q tile (128 x 64)
#pragma unroll
    for (int i = 0; i < 4; i++) {
        int idx = tid + i * 256;
        int r = idx >> 3, ch = idx & 7;
        cp16(sb + (uint32_t)(r * PADB + ch * 16), qB + (size_t)(q0 + r) * HS + ch * 8);
    }
    CP_COMMIT();

#define LOAD_TILE(st, kb_) do {                                            \
        uint32_t bs = sb + QTILE + (st) * ASTAGE;                          \
        for (int i_ = 0; i_ < 2; i_++) {                                   \
            int idx_ = tid + i_ * 256;                                     \
            int r_ = idx_ >> 3, ch_ = idx_ & 7;                            \
            uint32_t so_ = (uint32_t)(r_ * PADB + ch_ * 16);               \
            size_t kg_ = (size_t)((kb_) + r_) * HS + ch_ * 8;              \
            cp16(bs + so_, kB + kg_);                                      \
            cp16(bs + KVTILE + so_, vB + kg_);                             \
        } } while (0)

    LOAD_TILE(0, 0);
    CP_COMMIT();

    uint32_t qf[4][4];
    float of[8][4];
#pragma unroll
    for (int i = 0; i < 8; i++)
#pragma unroll
        for (int j = 0; j < 4; j++) of[i][j] = 0.f;
    float m0 = -1e30f, m1 = -1e30f, l0 = 0.f, l1 = 0.f;
    bool qload = false;

    int nkt = 2 * qt + 2;
    for (int kt = 0; kt < nkt; kt++) {
        int kb = kt * 64;
        CP_WAIT(0);
        __syncthreads();
        if (kt + 1 < nkt) { LOAD_TILE((kt + 1) & 1, kb + 64); CP_COMMIT(); }
        if (!qload) {
#pragma unroll
            for (int ks = 0; ks < 4; ks++)
                ldm4(qf[ks], sb + (uint32_t)((wm * 16) * PADB + ks * 32) + a_off);
            qload = true;
        }
        if (q0 + wm * 16 + 15 >= kb) {
            uint32_t base = sb + QTILE + (kt & 1) * ASTAGE;
            float sf[8][4];
#pragma unroll
            for (int i = 0; i < 8; i++)
#pragma unroll
                for (int j = 0; j < 4; j++) sf[i][j] = 0.f;

#pragma unroll
            for (int ks = 0; ks < 4; ks++) {
                uint32_t bh[4][4];
#pragma unroll
                for (int p = 0; p < 4; p++)
                    ldm4(bh[p], base + (uint32_t)((p * 16) * PADB + ks * 32) + b_off);
#pragma unroll
                for (int ni = 0; ni < 8; ni++)
                    mma_f16(sf[ni], qf[ks], &bh[ni >> 1][(ni & 1) * 2]);
            }

            int row0 = q0 + wm * 16 + t4, row1 = row0 + 8;
            bool needm = (kb + 63 > q0 + wm * 16);
            float mx0 = -1e30f, mx1 = -1e30f;
#pragma unroll
            for (int ni = 0; ni < 8; ni++) {
                int c = kb + ni * 8 + t2 * 2;
                float s0 = sf[ni][0] * SCLQK, s1 = sf[ni][1] * SCLQK;
                float s2 = sf[ni][2] * SCLQK, s3 = sf[ni][3] * SCLQK;
                if (needm) {
                    if (c > row0)     s0 = -1e30f;
                    if (c + 1 > row0) s1 = -1e30f;
                    if (c > row1)     s2 = -1e30f;
                    if (c + 1 > row1) s3 = -1e30f;
                }
                sf[ni][0] = s0; sf[ni][1] = s1; sf[ni][2] = s2; sf[ni][3] = s3;
                mx0 = fmaxf(mx0, fmaxf(s0, s1));
                mx1 = fmaxf(mx1, fmaxf(s2, s3));
            }
            mx0 = fmaxf(mx0, __shfl_xor_sync(0xffffffffu, mx0, 1));
            mx0 = fmaxf(mx0, __shfl_xor_sync(0xffffffffu, mx0, 2));
            mx1 = fmaxf(mx1, __shfl_xor_sync(0xffffffffu, mx1, 1));
            mx1 = fmaxf(mx1, __shfl_xor_sync(0xffffffffu, mx1, 2));
            float nm0 = fmaxf(m0, mx0), nm1 = fmaxf(m1, mx1);
            float cr0 = exp2f(m0 - nm0), cr1 = exp2f(m1 - nm1);
            m0 = nm0; m1 = nm1;
            l0 *= cr0; l1 *= cr1;
#pragma unroll
            for (int ni = 0; ni < 8; ni++) {
                float p0 = exp2f(sf[ni][0] - m0), p1 = exp2f(sf[ni][1] - m0);
                float p2 = exp2f(sf[ni][2] - m1), p3 = exp2f(sf[ni][3] - m1);
                sf[ni][0] = p0; sf[ni][1] = p1; sf[ni][2] = p2; sf[ni][3] = p3;
                l0 += p0 + p1; l1 += p2 + p3;
                of[ni][0] *= cr0; of[ni][1] *= cr0; of[ni][2] *= cr1; of[ni][3] *= cr1;
            }

#pragma unroll
            for (int ks2 = 0; ks2 < 4; ks2++) {
                int n0b = 2 * ks2, n1b = n0b + 1;
                uint32_t pah[4];
                pah[0] = pack2h(sf[n0b][0], sf[n0b][1]);
                pah[1] = pack2h(sf[n0b][2], sf[n0b][3]);
                pah[2] = pack2h(sf[n1b][0], sf[n1b][1]);
                pah[3] = pack2h(sf[n1b][2], sf[n1b][3]);
                uint32_t vh[4][4];
#pragma unroll
                for (int p = 0; p < 4; p++)
                    ldm4t(vh[p], base + KVTILE + (uint32_t)((ks2 * 16) * PADB + p * 32) + a_off);
#pragma unroll
                for (int ni = 0; ni < 8; ni++)
                    mma_f16(of[ni], pah, &vh[ni >> 1][(ni & 1) * 2]);
            }
        }
    }
#undef LOAD_TILE

    l0 += __shfl_xor_sync(0xffffffffu, l0, 1);
    l0 += __shfl_xor_sync(0xffffffffu, l0, 2);
    l1 += __shfl_xor_sync(0xffffffffu, l1, 1);
    l1 += __shfl_xor_sync(0xffffffffu, l1, 2);
    float inv0 = ASCALE / l0, inv1 = ASCALE / l1;

    int row0 = q0 + wm * 16 + t4;
#pragma unroll
    for (int ni = 0; ni < 8; ni++) {
        int col = h * HS + ni * 8 + t2 * 2;
        float s0 = of[ni][0] * inv0, s1 = of[ni][1] * inv0;
        float s2 = of[ni][2] * inv1, s3 = of[ni][3] * inv1;
        size_t o0 = ((size_t)(b * CTX) + row0) * DM + col;
        size_t o1 = o0 + (size_t)8 * DM;
        *(uint32_t*)(g_a16h + o0) = pack2h(s0, s1);
        *(uint32_t*)(g_a16h + o1) = pack2h(s2, s3);
    }
}

// ================= launch =================
extern "C" void kernel_launch(void* const* d_in, const int* in_sizes, int n_in,
                              void* d_out, int out_size)
{
    const float* x  = (const float*)d_in[0];
    const float* Wq = (const float*)d_in[1];
    const float* Wk = (const float*)d_in[2];
    const float* Wv = (const float*)d_in[3];
    const float* W1 = (const float*)d_in[4];
    const float* b1 = (const float*)d_in[5];
    const float* W2 = (const float*)d_in[6];
    const float* b2 = (const float*)d_in[7];
    float* out = (float*)d_out;

    f16 *q16, *k16, *v16;
    f16 *x16h, *a16h, *h16h, *bq16, *w116, *w216;
    cudaGetSymbolAddress((void**)&q16, g_q16);
    cudaGetSymbolAddress((void**)&k16, g_k16);
    cudaGetSymbolAddress((void**)&v16, g_v16);
    cudaGetSymbolAddress((void**)&x16h, g_x16h);
    cudaGetSymbolAddress((void**)&a16h, g_a16h);
    cudaGetSymbolAddress((void**)&h16h, g_h16h);
    cudaGetSymbolAddress((void**)&bq16, g_bq16);
    cudaGetSymbolAddress((void**)&w116, g_w116);
    cudaGetSymbolAddress((void**)&w216, g_w216);

    cudaFuncSetAttribute((const void*)gemm_f16<0>, cudaFuncAttributeMaxDynamicSharedMemorySize, GEMM_SMEM);
    cudaFuncSetAttribute((const void*)gemm_f16<1>, cudaFuncAttributeMaxDynamicSharedMemorySize, GEMM_SMEM);
    cudaFuncSetAttribute((const void*)gemm_f16<2>, cudaFuncAttributeMaxDynamicSharedMemorySize, GEMM_SMEM);
    cudaFuncSetAttribute(attn_mma, cudaFuncAttributeMaxDynamicSharedMemorySize, ATTN_SMEM);

    // conversions (pure streaming)
    conv_x_kernel<<<(size_t)MTOT * NEMB / 1024, 256>>>(x, x16h);
    conv_qkv_kernel<<<dim3(NEMB * DM / 1024, 3), 256>>>(Wq, Wk, Wv, bq16);
    conv_w_kernel<<<dim3((size_t)DM * FF / 1024, 2), 256>>>(W1, w116, W2, w216);

    // QKV: [8192,1024] @ [1024,3072] -> q/k/v single fp16 [B,H,T,D]
    gemm_f16<0><<<dim3(3 * DM / 256, MTOT / 128), 512, GEMM_SMEM>>>(
        x16h, bq16, nullptr,
        nullptr, nullptr,
        q16, k16, v16, 3 * DM, NEMB);

    // attention -> att fp16 x256
    attn_mma<<<dim3(CTX / 128, NH, BATCH), 256, ATTN_SMEM>>>();

    // FFN1: [8192,1024] @ [1024,4096] + b1 -> h fp16 x256
    gemm_f16<1><<<dim3(FF / 256, MTOT / 128), 512, GEMM_SMEM>>>(
        a16h, w116, b1,
        nullptr, h16h,
        nullptr, nullptr, nullptr, FF, DM);

    // FFN2: [8192,4096] @ [4096,1024] + b2, relu -> out
    gemm_f16<2><<<dim3(DM / 256, MTOT / 128), 512, GEMM_SMEM>>>(
        h16h, w216, b2,
        out, nullptr,
        nullptr, nullptr, nullptr, DM, FF);
}